// round 14
// baseline (speedup 1.0000x reference)
#include <cuda_runtime.h>

#define N 131072
#define D 128
#define K 1024
#define NITERS 10
#define CHUNK 512
#define CHUNKS (N / CHUNK)   /* 256 */

// ---------------- persistent device scratch (no allocations allowed) ----------------
__device__ float g_centroids[K * D];
__device__ float g_csq[K];
__device__ float g_xsq[N];
__device__ int   g_assign[N];
__device__ int   g_rank[N];
__device__ int   g_order[N];
__device__ int   g_hist[CHUNKS * K];
__device__ int   g_counts_i[K];
__device__ int   g_offs[K];

// ---------------- assignment kernel: argmin_k ||x - c_k||^2 ----------------
// 256 threads, 2 CTAs/SM. f32x2 lanes = TWO ADJACENT POINTS (a is a native
// LDS.64 from transposed X; no dup movs). Centroids pre-duplicated in smem
// ({v,v} per (d,c)) so b is a broadcast LDS.64. Per-thread micro-tile:
// 4 point-pairs x 8 centroids. Per d: 4 a-LDS + 8 b-LDS + 32 FMA2, no ALU.
// Scalar chains per (point,cent) accumulate ascending d with fma.rn (FROZEN).
#define XST_PITCH 130
#define XST_FLOATS (128 * XST_PITCH)          /* [128 d][130 pts] = 66560 B */
#define CD_FLOATS (32 * 128 * 2)              /* [32 d][128 c] float2 dup = 32768 B */
#define SMEM_FLOATS (XST_FLOATS + CD_FLOATS)
#define SMEM_BYTES (SMEM_FLOATS * 4)          /* 99328 B -> 2 CTAs/SM */

__global__ __launch_bounds__(256, 2)
void assign_kernel(const float* __restrict__ x) {
    extern __shared__ float sm[];
    float*  XsT = sm;                          // [128 d][XST_PITCH pts]
    float2* Cd  = (float2*)(sm + XST_FLOATS);  // [32 d][128 c] duplicated

    const int tid = threadIdx.x;
    const int tx = tid & 15;
    const int ty = tid >> 4;                   // 0..15
    const int pBase = blockIdx.x * 128;

    // Load X tile TRANSPOSED: XsT[d][p] (coalesced float4 global reads).
    #pragma unroll
    for (int s = 0; s < 16; s++) {
        const int idx = tid + s * 256;
        const int p = idx >> 5;                // 0..127
        const int g = idx & 31;                // d-group of 4
        float4 v = *(const float4*)(x + (size_t)(pBase + p) * D + g * 4);
        XsT[(g * 4 + 0) * XST_PITCH + p] = v.x;
        XsT[(g * 4 + 1) * XST_PITCH + p] = v.y;
        XsT[(g * 4 + 2) * XST_PITCH + p] = v.z;
        XsT[(g * 4 + 3) * XST_PITCH + p] = v.w;
    }

    // Point slots: s=0..7 -> point (s>>1)*32 + ty*2 + (s&1)
    float xs[8];
    float bestv[8];
    int   besti[8];
    #pragma unroll
    for (int s = 0; s < 8; s++) {
        xs[s] = g_xsq[pBase + (s >> 1) * 32 + ty * 2 + (s & 1)];
        bestv[s] = 3.4e38f;
        besti[s] = 0;
    }

    for (int chunk = 0; chunk < 8; chunk++) {
        const int c0 = chunk * 128;

        unsigned long long acc[4][8];
        #pragma unroll
        for (int i = 0; i < 4; i++)
            #pragma unroll
            for (int j = 0; j < 8; j++) acc[i][j] = 0ull;

        #pragma unroll
        for (int quarter = 0; quarter < 4; quarter++) {
            const int q0 = quarter * 32;
            __syncthreads();  // protect Cd before overwrite
            // Load centroid quarter, duplicated: Cd[dq][c] = {v, v}
            #pragma unroll
            for (int s = 0; s < 4; s++) {
                const int idx = tid + s * 256;
                const int c = idx >> 3;        // 0..127
                const int g = idx & 7;         // d-group of 4 within quarter
                float4 v = *(const float4*)(g_centroids +
                             (size_t)(c0 + c) * D + q0 + g * 4);
                Cd[(g * 4 + 0) * 128 + c] = make_float2(v.x, v.x);
                Cd[(g * 4 + 1) * 128 + c] = make_float2(v.y, v.y);
                Cd[(g * 4 + 2) * 128 + c] = make_float2(v.z, v.z);
                Cd[(g * 4 + 3) * 128 + c] = make_float2(v.w, v.w);
            }
            __syncthreads();

            #pragma unroll 2
            for (int d = 0; d < 32; d++) {
                unsigned long long b2[8];
                #pragma unroll
                for (int j = 0; j < 8; j++)
                    b2[j] = *(const unsigned long long*)(Cd + d * 128 + j * 16 + tx);
                #pragma unroll
                for (int i = 0; i < 4; i++) {
                    const unsigned long long a2 = *(const unsigned long long*)
                        (XsT + (q0 + d) * XST_PITCH + i * 32 + ty * 2);
                    #pragma unroll
                    for (int j = 0; j < 8; j++)
                        asm("fma.rn.f32x2 %0, %1, %2, %0;"
                            : "+l"(acc[i][j]) : "l"(a2), "l"(b2[j]));
                }
            }
        }

        // Epilogue: d = xsq - 2*dot + csq ; running argmin
        // (per-thread cents c0 + j*16 + tx visited ascending in j)
        float cs[8];
        #pragma unroll
        for (int j = 0; j < 8; j++) cs[j] = g_csq[c0 + j * 16 + tx];
        #pragma unroll
        for (int i = 0; i < 4; i++) {
            #pragma unroll
            for (int j = 0; j < 8; j++) {
                float v0, v1;  // v0 = point slot 2i, v1 = slot 2i+1
                asm("mov.b64 {%0, %1}, %2;" : "=f"(v0), "=f"(v1) : "l"(acc[i][j]));
                const int c = c0 + j * 16 + tx;
                const float d0 = fmaf(-2.f, v0, xs[2 * i]) + cs[j];
                const float d1 = fmaf(-2.f, v1, xs[2 * i + 1]) + cs[j];
                if (d0 < bestv[2 * i])     { bestv[2 * i] = d0;     besti[2 * i] = c; }
                if (d1 < bestv[2 * i + 1]) { bestv[2 * i + 1] = d1; besti[2 * i + 1] = c; }
            }
        }
    }

    // Cross-thread argmin reduction over the 16 tx lanes per point (lex order).
    __syncthreads();
    float* rv = sm;                         // [128][16] floats
    int*   ri = (int*)(sm + 128 * 16);      // [128][16] ints
    #pragma unroll
    for (int s = 0; s < 8; s++) {
        const int p = (s >> 1) * 32 + ty * 2 + (s & 1);
        rv[p * 16 + tx] = bestv[s];
        ri[p * 16 + tx] = besti[s];
    }
    __syncthreads();
    if (tid < 128) {
        float bv = rv[tid * 16];
        int   bi = ri[tid * 16];
        #pragma unroll
        for (int t = 1; t < 16; t++) {
            const float v = rv[tid * 16 + t];
            const int  ix = ri[tid * 16 + t];
            if (v < bv || (v == bv && ix < bi)) { bv = v; bi = ix; }
        }
        g_assign[pBase + tid] = bi;
    }
}

// ---------------- deterministic stable counting-sort of points by cluster ----------------
__global__ __launch_bounds__(256)
void rank_kernel() {
    __shared__ int hist[8][K];
    const int warp = threadIdx.x >> 5;
    const int lane = threadIdx.x & 31;
    const int chunk = blockIdx.x * 8 + warp;
    int* h = hist[warp];
    for (int i = lane; i < K; i += 32) h[i] = 0;
    __syncwarp();
    const int base_n = chunk * CHUNK;
    for (int g = 0; g < CHUNK / 32; g++) {
        const int n = base_n + g * 32 + lane;
        const int a = g_assign[n];
        const unsigned mask = __match_any_sync(0xffffffffu, a);
        const int before = __popc(mask & ((1u << lane) - 1u));
        const int b = h[a];
        __syncwarp();
        g_rank[n] = b + before;
        if (lane == (int)(__ffs(mask) - 1)) h[a] = b + __popc(mask);
        __syncwarp();
    }
    for (int i = lane; i < K; i += 32) g_hist[chunk * K + i] = h[i];
}

__global__ void chunkscan_kernel() {
    const int k = blockIdx.x * blockDim.x + threadIdx.x;  // 0..K-1
    if (k >= K) return;
    int run = 0;
    for (int c = 0; c < CHUNKS; c++) {
        const int t = g_hist[c * K + k];
        g_hist[c * K + k] = run;
        run += t;
    }
    g_counts_i[k] = run;
}

__global__ void offs_kernel() {
    __shared__ int s[K];
    const int k = threadIdx.x;
    const int my = g_counts_i[k];
    s[k] = my;
    __syncthreads();
    for (int o = 1; o < K; o <<= 1) {
        const int t = (k >= o) ? s[k - o] : 0;
        __syncthreads();
        s[k] += t;
        __syncthreads();
    }
    g_offs[k] = s[k] - my;
}

__global__ void scatter_kernel() {
    const int n = blockIdx.x * blockDim.x + threadIdx.x;
    if (n >= N) return;
    const int a = g_assign[n];
    const int chunk = n / CHUNK;
    const int slot = g_offs[a] + g_hist[chunk * K + a] + g_rank[n];
    g_order[slot] = n;
}

// Update: fp32 serial fold, ADJACENT-PAIR-SWAPPED ascending order (FROZEN —
// this exact order matched golden), then plain fp32 divide (0/0 -> NaN).
__global__ __launch_bounds__(128)
void update_kernel(const float* __restrict__ x) {
    const int k = blockIdx.x;
    const int d = threadIdx.x;
    const int cnt = g_counts_i[k];
    const int off = g_offs[k];
    float s = 0.f;
    for (int j = 0; j < cnt; j++) {
        int jj = j ^ 1;
        if (jj >= cnt) jj = j;          // odd tail element stays in place
        const int n = g_order[off + jj];
        s += x[(size_t)n * D + d];
    }
    g_centroids[k * D + d] = s / (float)cnt;
}

// ---------------- support kernels ----------------
__global__ void init_centroids_kernel(const float* __restrict__ x) {
    const int i = blockIdx.x * blockDim.x + threadIdx.x;
    if (i < K * D) g_centroids[i] = x[i];  // c0 = x[:K]
}

__global__ void xsq_kernel(const float* __restrict__ x) {
    const int gtid = blockIdx.x * blockDim.x + threadIdx.x;
    const int w = gtid >> 5;
    const int lane = gtid & 31;
    if (w < N) {
        float4 v = *(const float4*)(x + (size_t)w * D + lane * 4);
        float s = v.x * v.x + v.y * v.y + v.z * v.z + v.w * v.w;
        #pragma unroll
        for (int o = 16; o; o >>= 1) s += __shfl_down_sync(0xffffffffu, s, o);
        if (lane == 0) g_xsq[w] = s;
    }
}

// csq: serial fma chain (FROZEN — form used in the golden-matching run).
__global__ void csq_kernel() {
    const int k = blockIdx.x * blockDim.x + threadIdx.x;
    if (k < K) {
        const float* c = g_centroids + (size_t)k * D;
        float s = 0.f;
        #pragma unroll 8
        for (int d = 0; d < D; d++) s = fmaf(c[d], c[d], s);
        g_csq[k] = s;
    }
}

// Output (float32): [clusters(131072), centroids(131072), counts(1024)]
__global__ void writeout_kernel(float* __restrict__ out, int out_size) {
    const int i = blockIdx.x * blockDim.x + threadIdx.x;
    if (i >= out_size) return;
    if (i < N) {
        out[i] = (float)g_assign[i];
    } else if (i < N + K * D) {
        out[i] = g_centroids[i - N];
    } else if (i < N + K * D + K) {
        out[i] = (float)g_counts_i[i - N - K * D];
    }
}

// ---------------- launch ----------------
extern "C" void kernel_launch(void* const* d_in, const int* in_sizes, int n_in,
                              void* d_out, int out_size) {
    const float* x = (const float*)d_in[0];
    float* out = (float*)d_out;

    cudaFuncSetAttribute(assign_kernel,
                         cudaFuncAttributeMaxDynamicSharedMemorySize, SMEM_BYTES);

    init_centroids_kernel<<<(K * D + 255) / 256, 256>>>(x);
    xsq_kernel<<<(N * 32 + 255) / 256, 256>>>(x);
    csq_kernel<<<(K + 255) / 256, 256>>>();

    for (int it = 0; it < NITERS; it++) {
        assign_kernel<<<N / 128, 256, SMEM_BYTES>>>(x);
        rank_kernel<<<CHUNKS / 8, 256>>>();
        chunkscan_kernel<<<(K + 255) / 256, 256>>>();
        offs_kernel<<<1, K>>>();
        scatter_kernel<<<(N + 255) / 256, 256>>>();
        update_kernel<<<K, 128>>>(x);
        csq_kernel<<<(K + 255) / 256, 256>>>();
    }
    writeout_kernel<<<(out_size + 255) / 256, 256>>>(out, out_size);
}

// round 15
// speedup vs baseline: 1.3118x; 1.3118x over previous
#include <cuda_runtime.h>

#define N 131072
#define D 128
#define K 1024
#define NITERS 10
#define CHUNK 512
#define CHUNKS (N / CHUNK)   /* 256 */

// ---------------- persistent device scratch (no allocations allowed) ----------------
__device__ float g_centroids[K * D];
__device__ float g_csq[K];
__device__ float g_xsq[N];
__device__ int   g_assign[N];
__device__ int   g_rank[N];
__device__ int   g_order[N];
__device__ int   g_hist[CHUNKS * K];
__device__ int   g_counts_i[K];
__device__ int   g_offs[K];

// ---------------- assignment kernel: argmin_k ||x - c_k||^2 ----------------
// 512 threads, 2 CTAs/SM (8 warps/SMSP). tx = tid&15 (cent pairs), ty = tid>>4
// (point quads). Per-thread micro-tile: 4 CONTIGUOUS points x 8 cents (4 pairs).
// a: one LDS.128 from transposed X tile feeds 4 points; b: LDS.64 cent pairs.
// Scalar chains per (point,cent): ascending-d fma.rn.f32x2, lanes = cent parity
// (FROZEN numerics — identical to the golden-matching R11 kernel).
#define XST_PITCH 132
#define XST_FLOATS (128 * XST_PITCH)          /* [128 d][132 pts] = 67584 B */
#define CTH_PITCH 130
#define CTH_FLOATS (64 * CTH_PITCH)           /* [64 d][130 c] = 33280 B */
#define SMEM_FLOATS (XST_FLOATS + CTH_FLOATS)
#define SMEM_BYTES (SMEM_FLOATS * 4)          /* 100864 B -> 2 CTAs/SM */

__global__ __launch_bounds__(512, 2)
void assign_kernel(const float* __restrict__ x) {
    extern __shared__ float sm[];
    float* XsT = sm;                       // [128 d][XST_PITCH pts]
    float* CtH = sm + XST_FLOATS;          // [64 d][CTH_PITCH c]

    const int tid = threadIdx.x;
    const int tx = tid & 15;
    const int ty = tid >> 4;               // 0..31
    const int pBase = blockIdx.x * 128;

    // Load X tile TRANSPOSED: XsT[d][p] (coalesced float4 global reads).
    #pragma unroll
    for (int s = 0; s < 8; s++) {
        const int idx = tid + s * 512;
        const int p = idx >> 5;            // 0..127
        const int g = idx & 31;            // d-group of 4
        float4 v = *(const float4*)(x + (size_t)(pBase + p) * D + g * 4);
        XsT[(g * 4 + 0) * XST_PITCH + p] = v.x;
        XsT[(g * 4 + 1) * XST_PITCH + p] = v.y;
        XsT[(g * 4 + 2) * XST_PITCH + p] = v.z;
        XsT[(g * 4 + 3) * XST_PITCH + p] = v.w;
    }

    // Points: p = ty*4 + ii, ii in [0,4)
    float xs[4];
    float bestv[4];
    int   besti[4];
    #pragma unroll
    for (int ii = 0; ii < 4; ii++) {
        xs[ii] = g_xsq[pBase + ty * 4 + ii];
        bestv[ii] = 3.4e38f;
        besti[ii] = 0;
    }

    for (int chunk = 0; chunk < 8; chunk++) {
        const int c0 = chunk * 128;

        unsigned long long acc[4][4];      // [point ii][cent pair j]
        #pragma unroll
        for (int ii = 0; ii < 4; ii++)
            #pragma unroll
            for (int j = 0; j < 4; j++) acc[ii][j] = 0ull;

        #pragma unroll
        for (int half = 0; half < 2; half++) {
            const int h0 = half * 64;
            __syncthreads();  // protect CtH before overwrite
            // Load centroid half-chunk TRANSPOSED: CtH[d][cent], d in [h0,h0+64)
            {
                const int w = tid >> 5, lane = tid & 31;   // w 0..15
                const int cl = lane >> 4;                  // 0..1
                const int d4 = lane & 15;                  // float4 group along d
                #pragma unroll
                for (int s = 0; s < 4; s++) {
                    const int c = (w * 2 + cl) + s * 32;   // 0..127
                    float4 v = *(const float4*)(g_centroids +
                                 (size_t)(c0 + c) * D + h0 + d4 * 4);
                    CtH[(d4 * 4 + 0) * CTH_PITCH + c] = v.x;
                    CtH[(d4 * 4 + 1) * CTH_PITCH + c] = v.y;
                    CtH[(d4 * 4 + 2) * CTH_PITCH + c] = v.z;
                    CtH[(d4 * 4 + 3) * CTH_PITCH + c] = v.w;
                }
            }
            __syncthreads();

            #pragma unroll 4
            for (int d = 0; d < 64; d++) {
                const int dd = h0 + d;
                // b: 4 LDS.64 cent pairs
                unsigned long long b2[4];
                const float* crow = CtH + d * CTH_PITCH + tx * 2;
                #pragma unroll
                for (int j = 0; j < 4; j++)
                    b2[j] = *(const unsigned long long*)(crow + j * 32);
                // a: one LDS.128 = 4 contiguous points at dim dd
                const float4 av = *(const float4*)(XsT + dd * XST_PITCH + ty * 4);
                #pragma unroll
                for (int ii = 0; ii < 4; ii++) {
                    const float a = (ii == 0) ? av.x : (ii == 1) ? av.y
                                  : (ii == 2) ? av.z : av.w;
                    unsigned long long a2;
                    asm("mov.b64 %0, {%1, %1};" : "=l"(a2) : "f"(a));
                    #pragma unroll
                    for (int j = 0; j < 4; j++)
                        asm("fma.rn.f32x2 %0, %1, %2, %0;"
                            : "+l"(acc[ii][j]) : "l"(a2), "l"(b2[j]));
                }
            }
        }

        // Epilogue: d = xsq - 2*dot + csq ; running argmin (ascending j per thread)
        float cs0[4], cs1[4];
        int   cb[4];
        #pragma unroll
        for (int j = 0; j < 4; j++) {
            const int c = c0 + j * 32 + tx * 2;
            cb[j] = c;
            cs0[j] = g_csq[c];
            cs1[j] = g_csq[c + 1];
        }
        #pragma unroll
        for (int ii = 0; ii < 4; ii++) {
            #pragma unroll
            for (int j = 0; j < 4; j++) {
                float v0, v1;
                asm("mov.b64 {%0, %1}, %2;" : "=f"(v0), "=f"(v1) : "l"(acc[ii][j]));
                const float d0 = fmaf(-2.f, v0, xs[ii]) + cs0[j];
                const float d1 = fmaf(-2.f, v1, xs[ii]) + cs1[j];
                if (d0 < bestv[ii]) { bestv[ii] = d0; besti[ii] = cb[j]; }
                if (d1 < bestv[ii]) { bestv[ii] = d1; besti[ii] = cb[j] + 1; }
            }
        }
    }

    // Cross-thread argmin reduction over the 16 tx lanes per point (lex order).
    __syncthreads();
    float* rv = sm;                         // [128][16] floats
    int*   ri = (int*)(sm + 128 * 16);      // [128][16] ints
    #pragma unroll
    for (int ii = 0; ii < 4; ii++) {
        const int p = ty * 4 + ii;
        rv[p * 16 + tx] = bestv[ii];
        ri[p * 16 + tx] = besti[ii];
    }
    __syncthreads();
    if (tid < 128) {
        float bv = rv[tid * 16];
        int   bi = ri[tid * 16];
        #pragma unroll
        for (int t = 1; t < 16; t++) {
            const float v = rv[tid * 16 + t];
            const int  ix = ri[tid * 16 + t];
            if (v < bv || (v == bv && ix < bi)) { bv = v; bi = ix; }
        }
        g_assign[pBase + tid] = bi;
    }
}

// ---------------- deterministic stable counting-sort of points by cluster ----------------
__global__ __launch_bounds__(256)
void rank_kernel() {
    __shared__ int hist[8][K];
    const int warp = threadIdx.x >> 5;
    const int lane = threadIdx.x & 31;
    const int chunk = blockIdx.x * 8 + warp;
    int* h = hist[warp];
    for (int i = lane; i < K; i += 32) h[i] = 0;
    __syncwarp();
    const int base_n = chunk * CHUNK;
    for (int g = 0; g < CHUNK / 32; g++) {
        const int n = base_n + g * 32 + lane;
        const int a = g_assign[n];
        const unsigned mask = __match_any_sync(0xffffffffu, a);
        const int before = __popc(mask & ((1u << lane) - 1u));
        const int b = h[a];
        __syncwarp();
        g_rank[n] = b + before;
        if (lane == (int)(__ffs(mask) - 1)) h[a] = b + __popc(mask);
        __syncwarp();
    }
    for (int i = lane; i < K; i += 32) g_hist[chunk * K + i] = h[i];
}

__global__ void chunkscan_kernel() {
    const int k = blockIdx.x * blockDim.x + threadIdx.x;  // 0..K-1
    if (k >= K) return;
    int run = 0;
    for (int c = 0; c < CHUNKS; c++) {
        const int t = g_hist[c * K + k];
        g_hist[c * K + k] = run;
        run += t;
    }
    g_counts_i[k] = run;
}

__global__ void offs_kernel() {
    __shared__ int s[K];
    const int k = threadIdx.x;
    const int my = g_counts_i[k];
    s[k] = my;
    __syncthreads();
    for (int o = 1; o < K; o <<= 1) {
        const int t = (k >= o) ? s[k - o] : 0;
        __syncthreads();
        s[k] += t;
        __syncthreads();
    }
    g_offs[k] = s[k] - my;
}

__global__ void scatter_kernel() {
    const int n = blockIdx.x * blockDim.x + threadIdx.x;
    if (n >= N) return;
    const int a = g_assign[n];
    const int chunk = n / CHUNK;
    const int slot = g_offs[a] + g_hist[chunk * K + a] + g_rank[n];
    g_order[slot] = n;
}

// Update + csq fused. Update: fp32 serial fold, ADJACENT-PAIR-SWAPPED ascending
// order (FROZEN — matched golden), plain fp32 divide (0/0 -> NaN). csq: serial
// fmaf chain over the freshly rounded fp32 centroid (FROZEN form), by thread 0.
__global__ __launch_bounds__(128)
void update_kernel(const float* __restrict__ x) {
    __shared__ float cent[128];
    const int k = blockIdx.x;
    const int d = threadIdx.x;
    const int cnt = g_counts_i[k];
    const int off = g_offs[k];
    float s = 0.f;
    for (int j = 0; j < cnt; j++) {
        int jj = j ^ 1;
        if (jj >= cnt) jj = j;          // odd tail element stays in place
        const int n = g_order[off + jj];
        s += x[(size_t)n * D + d];
    }
    const float c = s / (float)cnt;
    g_centroids[k * D + d] = c;
    cent[d] = c;
    __syncthreads();
    if (d == 0) {
        float q = 0.f;
        #pragma unroll 8
        for (int dd = 0; dd < D; dd++) q = fmaf(cent[dd], cent[dd], q);
        g_csq[k] = q;
    }
}

// ---------------- support kernels ----------------
__global__ void init_centroids_kernel(const float* __restrict__ x) {
    const int i = blockIdx.x * blockDim.x + threadIdx.x;
    if (i < K * D) g_centroids[i] = x[i];  // c0 = x[:K]
}

__global__ void xsq_kernel(const float* __restrict__ x) {
    const int gtid = blockIdx.x * blockDim.x + threadIdx.x;
    const int w = gtid >> 5;
    const int lane = gtid & 31;
    if (w < N) {
        float4 v = *(const float4*)(x + (size_t)w * D + lane * 4);
        float s = v.x * v.x + v.y * v.y + v.z * v.z + v.w * v.w;
        #pragma unroll
        for (int o = 16; o; o >>= 1) s += __shfl_down_sync(0xffffffffu, s, o);
        if (lane == 0) g_xsq[w] = s;
    }
}

// csq (initial centroids only): serial fma chain (FROZEN form).
__global__ void csq_kernel() {
    const int k = blockIdx.x * blockDim.x + threadIdx.x;
    if (k < K) {
        const float* c = g_centroids + (size_t)k * D;
        float s = 0.f;
        #pragma unroll 8
        for (int d = 0; d < D; d++) s = fmaf(c[d], c[d], s);
        g_csq[k] = s;
    }
}

// Output (float32): [clusters(131072), centroids(131072), counts(1024)]
__global__ void writeout_kernel(float* __restrict__ out, int out_size) {
    const int i = blockIdx.x * blockDim.x + threadIdx.x;
    if (i >= out_size) return;
    if (i < N) {
        out[i] = (float)g_assign[i];
    } else if (i < N + K * D) {
        out[i] = g_centroids[i - N];
    } else if (i < N + K * D + K) {
        out[i] = (float)g_counts_i[i - N - K * D];
    }
}

// ---------------- launch ----------------
extern "C" void kernel_launch(void* const* d_in, const int* in_sizes, int n_in,
                              void* d_out, int out_size) {
    const float* x = (const float*)d_in[0];
    float* out = (float*)d_out;

    cudaFuncSetAttribute(assign_kernel,
                         cudaFuncAttributeMaxDynamicSharedMemorySize, SMEM_BYTES);

    init_centroids_kernel<<<(K * D + 255) / 256, 256>>>(x);
    xsq_kernel<<<(N * 32 + 255) / 256, 256>>>(x);
    csq_kernel<<<(K + 255) / 256, 256>>>();

    for (int it = 0; it < NITERS; it++) {
        assign_kernel<<<N / 128, 512, SMEM_BYTES>>>(x);
        rank_kernel<<<CHUNKS / 8, 256>>>();
        chunkscan_kernel<<<(K + 255) / 256, 256>>>();
        offs_kernel<<<1, K>>>();
        scatter_kernel<<<(N + 255) / 256, 256>>>();
        update_kernel<<<K, 128>>>(x);
    }
    writeout_kernel<<<(out_size + 255) / 256, 256>>>(out, out_size);
}